// round 15
// baseline (speedup 1.0000x reference)
#include <cuda_runtime.h>
#include <cuda_fp16.h>
#include <stdint.h>

#define NTOK 8192
#define D_   1024
#define H_   2048
#define E_   8
#define KBIG (E_*H_)
#define KSPLIT 4

#define BM 128
#define BN 128
#define BKH 64
#define OPB (128*128)
#define STAGE_BYTES (2*OPB)
#define NSTAGE 3
#define SMEM_BYTES (NSTAGE*STAGE_BYTES)

// merged-preamble grid layout
#define GB_GATE 1024                   // 1024 blocks x 256 thr, 1 warp/token
#define GB_W1   (64*32*8)              // 16384
#define GB_W2   (512*32)               // 16384
#define GB_ALL  (GB_GATE+GB_W1+GB_W2)  // 33792

// ------------------ scratch ------------------
__device__ float g_gate[NTOK*E_];
__device__ __half g_x16[(size_t)NTOK*D_];
__device__ __half g_w1t16[(size_t)E_*H_*D_];   // [E][H][D]
__device__ __half g_w2t16[(size_t)D_*KBIG];    // [D][KBIG]
__device__ __half g_hs16[(size_t)NTOK*KBIG];   // [NTOK][KBIG]
__device__ __half g_part[KSPLIT][(size_t)NTOK*D_];   // fp16 split-K partials

// ------------------ PTX helpers ------------------
__device__ __forceinline__ uint32_t smem_u32(const void* p){
    uint32_t a;
    asm("{ .reg .u64 t; cvta.to.shared.u64 t, %1; cvt.u32.u64 %0, t; }" : "=r"(a) : "l"(p));
    return a;
}
__device__ __forceinline__ void cpa(uint32_t dst, const void* src){
    asm volatile("cp.async.cg.shared.global [%0], [%1], 16;" :: "r"(dst), "l"(src));
}
__device__ __forceinline__ void ldsm4(uint32_t* r, uint32_t addr){
    asm volatile("ldmatrix.sync.aligned.m8n8.x4.shared.b16 {%0,%1,%2,%3}, [%4];"
        : "=r"(r[0]), "=r"(r[1]), "=r"(r[2]), "=r"(r[3]) : "r"(addr));
}
__device__ __forceinline__ void mma16816(float* c, const uint32_t* a, const uint32_t* b){
    asm volatile("mma.sync.aligned.m16n8k16.row.col.f32.f16.f16.f32 "
        "{%0,%1,%2,%3}, {%4,%5,%6,%7}, {%8,%9}, {%0,%1,%2,%3};"
        : "+f"(c[0]), "+f"(c[1]), "+f"(c[2]), "+f"(c[3])
        : "r"(a[0]), "r"(a[1]), "r"(a[2]), "r"(a[3]), "r"(b[0]), "r"(b[1]));
}
__device__ __forceinline__ uint32_t pkh(float a, float b){
    __half2 h = __halves2half2(__float2half_rn(a), __float2half_rn(b));
    return *(uint32_t*)&h;
}

// ------------------ merged preamble: gate+cvt_x | cvt_w1 | cvt_w2 ------------------
__global__ __launch_bounds__(256)
void preamble_kernel(const float* __restrict__ x,  const float* __restrict__ Wg,
                     const float* __restrict__ bg, const float* __restrict__ W1,
                     const float* __restrict__ W2){
    __shared__ float t[32][33];
    int bid = blockIdx.x;
    int tid = threadIdx.x;

    if (bid < GB_GATE){
        // ---- gate = softmax(x@Wg + bg), fused x->fp16 convert (1 warp/token) ----
        int gw = (bid*256 + tid) >> 5;
        int lane = tid & 31;
        const float* xr = x + (size_t)gw * D_;
        __half* xo = g_x16 + (size_t)gw * D_;
        float acc[E_];
#pragma unroll
        for (int e=0;e<E_;e++) acc[e]=0.f;
#pragma unroll
        for (int k0=0;k0<D_;k0+=128){
            int k = k0 + lane*4;
            float4 xv = *(const float4*)(xr + k);
            uint2 hw = make_uint2(pkh(xv.x, xv.y), pkh(xv.z, xv.w));
            *(uint2*)(xo + k) = hw;
            float xs[4] = {xv.x, xv.y, xv.z, xv.w};
#pragma unroll
            for (int j=0;j<4;j++){
                float4 w0 = *(const float4*)(Wg + (k+j)*E_);
                float4 w1 = *(const float4*)(Wg + (k+j)*E_ + 4);
                acc[0]=fmaf(xs[j],w0.x,acc[0]); acc[1]=fmaf(xs[j],w0.y,acc[1]);
                acc[2]=fmaf(xs[j],w0.z,acc[2]); acc[3]=fmaf(xs[j],w0.w,acc[3]);
                acc[4]=fmaf(xs[j],w1.x,acc[4]); acc[5]=fmaf(xs[j],w1.y,acc[5]);
                acc[6]=fmaf(xs[j],w1.z,acc[6]); acc[7]=fmaf(xs[j],w1.w,acc[7]);
            }
        }
#pragma unroll
        for (int e=0;e<E_;e++)
#pragma unroll
            for (int o=16;o;o>>=1) acc[e] += __shfl_xor_sync(0xFFFFFFFFu, acc[e], o);
        if (lane==0){
            float m=-1e30f;
#pragma unroll
            for (int e=0;e<E_;e++){ acc[e]+=bg[e]; m=fmaxf(m,acc[e]); }
            float s=0.f;
#pragma unroll
            for (int e=0;e<E_;e++){ acc[e]=__expf(acc[e]-m); s+=acc[e]; }
            float inv=1.f/s;
#pragma unroll
            for (int e=0;e<E_;e++) g_gate[gw*E_+e]=acc[e]*inv;
        }
    } else if (bid < GB_GATE + GB_W1){
        // ---- cvt_w1: [E,D,H] -> [E,H,D] fp16 (32x32 transpose tile) ----
        int i = bid - GB_GATE;
        int bx = i & 63, by = (i>>6) & 31, e = i >> 11;
        int h0 = bx*32, d0 = by*32;
        const float* src = W1 + (size_t)e*D_*H_;
        {
            int r = tid>>3, c4 = tid&7;
            float4 v = *(const float4*)(src + (size_t)(d0+r)*H_ + h0 + c4*4);
            t[r][c4*4+0]=v.x; t[r][c4*4+1]=v.y; t[r][c4*4+2]=v.z; t[r][c4*4+3]=v.w;
        }
        __syncthreads();
        __half* dst = g_w1t16 + (size_t)e*H_*D_;
#pragma unroll
        for (int q=0;q<2;q++){
            int u = tid + q*256;
            int h = u>>4, dp = u&15;
            __half2 v = __halves2half2(__float2half_rn(t[2*dp][h]), __float2half_rn(t[2*dp+1][h]));
            *(__half2*)(dst + (size_t)(h0+h)*D_ + d0 + 2*dp) = v;
        }
    } else {
        // ---- cvt_w2: [KBIG,D] -> [D,KBIG] fp16 ----
        int j = bid - GB_GATE - GB_W1;
        int bx = j & 511, by = j >> 9;
        int k0 = bx*32, d0 = by*32;
        {
            int r = tid>>3, c4 = tid&7;
            float4 v = *(const float4*)(W2 + (size_t)(k0+r)*D_ + d0 + c4*4);
            t[r][c4*4+0]=v.x; t[r][c4*4+1]=v.y; t[r][c4*4+2]=v.z; t[r][c4*4+3]=v.w;
        }
        __syncthreads();
#pragma unroll
        for (int q=0;q<2;q++){
            int u = tid + q*256;
            int d = u>>4, kp = u&15;
            __half2 v = __halves2half2(__float2half_rn(t[2*kp][d]), __float2half_rn(t[2*kp+1][d]));
            *(__half2*)(g_w2t16 + (size_t)(d0+d)*KBIG + k0 + 2*kp) = v;
        }
    }
}

// ------------------ stage loader (128 threads): 128 rows x 128B per operand, XOR swizzle ------------------
__device__ __forceinline__ void load_stage(const __half* __restrict__ A,
                                           const __half* __restrict__ B,
                                           int ldK, uint32_t sb, int k0, int tid){
#pragma unroll
    for (int i=0;i<8;i++){
        int idx = tid + i*128;
        int r = idx>>3, c = idx&7;
        uint32_t off = (uint32_t)(r*128 + ((c*16) ^ ((r&7)<<4)));
        cpa(sb + off, A + (size_t)r*ldK + k0 + c*8);
    }
#pragma unroll
    for (int i=0;i<8;i++){
        int idx = tid + i*128;
        int r = idx>>3, c = idx&7;
        uint32_t off = (uint32_t)(r*128 + ((c*16) ^ ((r&7)<<4)));
        cpa(sb + OPB + off, B + (size_t)r*ldK + k0 + c*8);
    }
}

// ------------------ fp16 HMMA GEMM (R10-proven mainloop, byte-identical) ------------------
// MODE 0: hs = relu(x@W1T[e]+b1)*gate  (K=D_)
// MODE 1: partial = hs@W2T over K-quarter blockIdx.z -> g_part[z] (fp16)
template<int MODE>
__global__ __launch_bounds__(128, 2)
void gemm_f16(const float* __restrict__ bias, float* __restrict__ outp){
    extern __shared__ char smem[];
    uint32_t sbase = smem_u32(smem);
    int tid = threadIdx.x;
    int lane = tid & 31, warp = tid >> 5;
    int wm = warp & 1, wn = warp >> 1;

    int n0 = blockIdx.y * BM;
    int c0 = blockIdx.x * BN;

    const __half *Ag, *Bg;
    int K, ldK;
    if (MODE == 0){
        Ag = g_x16 + (size_t)n0 * D_;
        Bg = g_w1t16 + (size_t)blockIdx.z*H_*D_ + (size_t)c0 * D_;
        K = D_; ldK = D_;
    } else {
        int kz = blockIdx.z;
        Ag = g_hs16 + (size_t)n0 * KBIG + (size_t)kz*(KBIG/KSPLIT);
        Bg = g_w2t16 + (size_t)c0 * KBIG + (size_t)kz*(KBIG/KSPLIT);
        K = KBIG/KSPLIT; ldK = KBIG;
    }
    const int NC = K / BKH;

    float acc[4][8][4];
#pragma unroll
    for (int i=0;i<4;i++)
#pragma unroll
        for (int j=0;j<8;j++)
#pragma unroll
            for (int q=0;q<4;q++) acc[i][j][q] = 0.f;

    int arow = wm*64 + (lane&15);
    uint32_t axor = (uint32_t)((arow&7)<<4);
    int brow = wn*64 + ((lane>>4)<<3) + (lane&7);
    uint32_t bxor = (uint32_t)((brow&7)<<4);
    uint32_t acol0 = (uint32_t)((lane>>4)*16);
    uint32_t bcol0 = (uint32_t)(((lane>>3)&1)*16);

    load_stage(Ag, Bg, ldK, sbase + 0*STAGE_BYTES, 0*BKH, tid);
    asm volatile("cp.async.commit_group;");
    load_stage(Ag, Bg, ldK, sbase + 1*STAGE_BYTES, 1*BKH, tid);
    asm volatile("cp.async.commit_group;");

    int sidx = 0;
    for (int kt=0; kt<NC; kt++){
        asm volatile("cp.async.wait_group 1;");
        __syncthreads();

        uint32_t st = sbase + (uint32_t)sidx*STAGE_BYTES;
        uint32_t arow0 = st + (uint32_t)(arow*128);
        uint32_t brow0 = st + (uint32_t)(OPB + brow*128);

        uint32_t af[2][4][4], bf[2][4][4];
#pragma unroll
        for (int mi=0; mi<4; mi++) ldsm4(af[0][mi], arow0 + mi*(16*128) + (acol0 ^ axor));
#pragma unroll
        for (int np=0; np<4; np++) ldsm4(bf[0][np], brow0 + np*(16*128) + (bcol0 ^ bxor));

        int snext = sidx + 2; if (snext >= NSTAGE) snext -= NSTAGE;
        if (kt+2 < NC)
            load_stage(Ag, Bg, ldK, sbase + snext*STAGE_BYTES, (kt+2)*BKH, tid);
        asm volatile("cp.async.commit_group;");

#pragma unroll
        for (int ks=0; ks<4; ks++){
            int cur = ks & 1, nxt = cur ^ 1;
            if (ks < 3){
                uint32_t ac = (uint32_t)((ks+1)*32) + acol0;
                uint32_t bc = (uint32_t)((ks+1)*32) + bcol0;
#pragma unroll
                for (int mi=0; mi<4; mi++) ldsm4(af[nxt][mi], arow0 + mi*(16*128) + (ac ^ axor));
#pragma unroll
                for (int np=0; np<4; np++) ldsm4(bf[nxt][np], brow0 + np*(16*128) + (bc ^ bxor));
            }
#pragma unroll
            for (int mi=0; mi<4; mi++)
#pragma unroll
                for (int ni=0; ni<8; ni++)
                    mma16816(acc[mi][ni], af[cur][mi], &bf[cur][ni>>1][(ni&1)*2]);
        }
        sidx = snext - 1; if (sidx < 0) sidx += NSTAGE;
    }
    asm volatile("cp.async.wait_group 0;");
    __syncthreads();

    if (MODE == 0){
        int e = blockIdx.z;
        float* bsm = (float*)smem;
        bsm[tid] = bias[(size_t)e*H_ + c0 + tid];
        __syncthreads();
#pragma unroll
        for (int mi=0; mi<4; mi++){
#pragma unroll
            for (int h=0; h<2; h++){
                int tok = n0 + wm*64 + mi*16 + (lane>>2) + h*8;
                float gt = g_gate[tok*E_ + e];
                __half* dst = g_hs16 + (size_t)tok*KBIG + (size_t)e*H_ + c0;
#pragma unroll
                for (int ni=0; ni<8; ni++){
                    int col = wn*64 + ni*8 + (lane&3)*2;
                    float v0 = fmaxf(acc[mi][ni][h*2+0] + bsm[col],   0.f) * gt;
                    float v1 = fmaxf(acc[mi][ni][h*2+1] + bsm[col+1], 0.f) * gt;
                    *(__half2*)(dst + col) = __halves2half2(__float2half_rn(v0), __float2half_rn(v1));
                }
            }
        }
    } else {
        __half* dstbase = g_part[blockIdx.z];
#pragma unroll
        for (int mi=0; mi<4; mi++){
#pragma unroll
            for (int h=0; h<2; h++){
                int tok = n0 + wm*64 + mi*16 + (lane>>2) + h*8;
                __half* dst = dstbase + (size_t)tok*D_ + c0;
#pragma unroll
                for (int ni=0; ni<8; ni++){
                    int col = wn*64 + ni*8 + (lane&3)*2;
                    *(__half2*)(dst + col) = __halves2half2(
                        __float2half_rn(acc[mi][ni][h*2+0]),
                        __float2half_rn(acc[mi][ni][h*2+1]));
                }
            }
        }
    }
}

// ------------------ reduce: 128 thr, 8 cols/thread, 16B partial loads ------------------
__global__ __launch_bounds__(128)
void reduce_kernel(const float* __restrict__ b2, float* __restrict__ outp){
    int tok = blockIdx.x;
    int c = threadIdx.x * 8;
    const float4* gp = (const float4*)(g_gate + (size_t)tok*E_);
    float4 ga = gp[0], gb = gp[1];
    float gt[8] = {ga.x,ga.y,ga.z,ga.w,gb.x,gb.y,gb.z,gb.w};

    float r[8];
#pragma unroll
    for (int i=0;i<8;i++) r[i] = 0.f;
#pragma unroll
    for (int z=0; z<KSPLIT; z++){
        uint4 p = *(const uint4*)(g_part[z] + (size_t)tok*D_ + c);
        float2 a0 = __half22float2(*(__half2*)&p.x);
        float2 a1 = __half22float2(*(__half2*)&p.y);
        float2 a2 = __half22float2(*(__half2*)&p.z);
        float2 a3 = __half22float2(*(__half2*)&p.w);
        r[0]+=a0.x; r[1]+=a0.y; r[2]+=a1.x; r[3]+=a1.y;
        r[4]+=a2.x; r[5]+=a2.y; r[6]+=a3.x; r[7]+=a3.y;
    }
#pragma unroll
    for (int e=0;e<E_;e++){
        float4 b0 = *(const float4*)(b2 + (size_t)e*D_ + c);
        float4 b1 = *(const float4*)(b2 + (size_t)e*D_ + c + 4);
        r[0] = fmaf(gt[e], b0.x, r[0]);
        r[1] = fmaf(gt[e], b0.y, r[1]);
        r[2] = fmaf(gt[e], b0.z, r[2]);
        r[3] = fmaf(gt[e], b0.w, r[3]);
        r[4] = fmaf(gt[e], b1.x, r[4]);
        r[5] = fmaf(gt[e], b1.y, r[5]);
        r[6] = fmaf(gt[e], b1.z, r[6]);
        r[7] = fmaf(gt[e], b1.w, r[7]);
    }
    float* dst = outp + (size_t)tok*D_ + c;
    *(float4*)(dst)     = make_float4(r[0], r[1], r[2], r[3]);
    *(float4*)(dst + 4) = make_float4(r[4], r[5], r[6], r[7]);
}

// ---------------------------------------------------------------------------
extern "C" void kernel_launch(void* const* d_in, const int* in_sizes, int n_in,
                              void* d_out, int out_size)
{
    const float* x  = (const float*)d_in[0];
    const float* Wg = (const float*)d_in[1];
    const float* bg = (const float*)d_in[2];
    const float* W1 = (const float*)d_in[3];
    const float* b1 = (const float*)d_in[4];
    const float* W2 = (const float*)d_in[5];
    const float* b2 = (const float*)d_in[6];
    float* out = (float*)d_out;

    cudaFuncSetAttribute(gemm_f16<0>, cudaFuncAttributeMaxDynamicSharedMemorySize, SMEM_BYTES);
    cudaFuncSetAttribute(gemm_f16<1>, cudaFuncAttributeMaxDynamicSharedMemorySize, SMEM_BYTES);

    preamble_kernel<<<GB_ALL, 256>>>(x, Wg, bg, W1, W2);

    gemm_f16<0><<<dim3(H_/BN, NTOK/BM, E_), 128, SMEM_BYTES>>>(b1, nullptr);
    gemm_f16<1><<<dim3(D_/BN, NTOK/BM, KSPLIT), 128, SMEM_BYTES>>>(nullptr, nullptr);
    reduce_kernel<<<NTOK, 128>>>(b2, out);
}

// round 16
// speedup vs baseline: 1.0381x; 1.0381x over previous
#include <cuda_runtime.h>
#include <cuda_fp16.h>
#include <stdint.h>

#define NTOK 8192
#define D_   1024
#define H_   2048
#define E_   8
#define KBIG (E_*H_)
#define KSPLIT 4

#define BM 128
#define BN 128
#define BKH 64
#define OPB (128*128)
#define STAGE_BYTES (2*OPB)
#define NSTAGE 3
#define SMEM_BYTES (NSTAGE*STAGE_BYTES)

// merged-preamble grid layout
#define GB_GATE 1024                   // 1024 blocks x 256 thr, 1 warp/token
#define GB_W1   (64*32*8)              // 16384
#define GB_W2   (512*32)               // 16384
#define GB_ALL  (GB_GATE+GB_W1+GB_W2)  // 33792

// ------------------ scratch ------------------
__device__ float g_gate[NTOK*E_];
__device__ __half g_x16[(size_t)NTOK*D_];
__device__ __half g_w1t16[(size_t)E_*H_*D_];   // [E][H][D]
__device__ __half g_w2t16[(size_t)D_*KBIG];    // [D][KBIG]
__device__ __half g_hs16[(size_t)NTOK*KBIG];   // [NTOK][KBIG]
__device__ __half g_part[KSPLIT][(size_t)NTOK*D_];   // fp16 split-K partials

// ------------------ PTX helpers ------------------
__device__ __forceinline__ uint32_t smem_u32(const void* p){
    uint32_t a;
    asm("{ .reg .u64 t; cvta.to.shared.u64 t, %1; cvt.u32.u64 %0, t; }" : "=r"(a) : "l"(p));
    return a;
}
__device__ __forceinline__ void cpa(uint32_t dst, const void* src){
    asm volatile("cp.async.cg.shared.global [%0], [%1], 16;" :: "r"(dst), "l"(src));
}
__device__ __forceinline__ void ldsm4(uint32_t* r, uint32_t addr){
    asm volatile("ldmatrix.sync.aligned.m8n8.x4.shared.b16 {%0,%1,%2,%3}, [%4];"
        : "=r"(r[0]), "=r"(r[1]), "=r"(r[2]), "=r"(r[3]) : "r"(addr));
}
__device__ __forceinline__ void mma16816(float* c, const uint32_t* a, const uint32_t* b){
    asm volatile("mma.sync.aligned.m16n8k16.row.col.f32.f16.f16.f32 "
        "{%0,%1,%2,%3}, {%4,%5,%6,%7}, {%8,%9}, {%0,%1,%2,%3};"
        : "+f"(c[0]), "+f"(c[1]), "+f"(c[2]), "+f"(c[3])
        : "r"(a[0]), "r"(a[1]), "r"(a[2]), "r"(a[3]), "r"(b[0]), "r"(b[1]));
}

// ------------------ merged preamble: gate+cvt_x | cvt_w1 | cvt_w2 ------------------
__global__ __launch_bounds__(256)
void preamble_kernel(const float* __restrict__ x,  const float* __restrict__ Wg,
                     const float* __restrict__ bg, const float* __restrict__ W1,
                     const float* __restrict__ W2){
    __shared__ float t[32][33];
    int bid = blockIdx.x;
    int tid = threadIdx.x;

    if (bid < GB_GATE){
        // ---- gate = softmax(x@Wg + bg), fused x->fp16 convert (1 warp/token) ----
        int gw = (bid*256 + tid) >> 5;
        int lane = tid & 31;
        const float* xr = x + (size_t)gw * D_;
        __half* xo = g_x16 + (size_t)gw * D_;
        float acc[E_];
#pragma unroll
        for (int e=0;e<E_;e++) acc[e]=0.f;
        for (int k=lane;k<D_;k+=32){
            float xv = xr[k];
            xo[k] = __float2half_rn(xv);
            float4 w0 = *(const float4*)(Wg + k*E_);
            float4 w1 = *(const float4*)(Wg + k*E_ + 4);
            acc[0]=fmaf(xv,w0.x,acc[0]); acc[1]=fmaf(xv,w0.y,acc[1]);
            acc[2]=fmaf(xv,w0.z,acc[2]); acc[3]=fmaf(xv,w0.w,acc[3]);
            acc[4]=fmaf(xv,w1.x,acc[4]); acc[5]=fmaf(xv,w1.y,acc[5]);
            acc[6]=fmaf(xv,w1.z,acc[6]); acc[7]=fmaf(xv,w1.w,acc[7]);
        }
#pragma unroll
        for (int e=0;e<E_;e++)
#pragma unroll
            for (int o=16;o;o>>=1) acc[e] += __shfl_xor_sync(0xFFFFFFFFu, acc[e], o);
        if (lane==0){
            float m=-1e30f;
#pragma unroll
            for (int e=0;e<E_;e++){ acc[e]+=bg[e]; m=fmaxf(m,acc[e]); }
            float s=0.f;
#pragma unroll
            for (int e=0;e<E_;e++){ acc[e]=__expf(acc[e]-m); s+=acc[e]; }
            float inv=1.f/s;
#pragma unroll
            for (int e=0;e<E_;e++) g_gate[gw*E_+e]=acc[e]*inv;
        }
    } else if (bid < GB_GATE + GB_W1){
        // ---- cvt_w1: [E,D,H] -> [E,H,D] fp16 (32x32 transpose tile) ----
        int i = bid - GB_GATE;
        int bx = i & 63, by = (i>>6) & 31, e = i >> 11;
        int h0 = bx*32, d0 = by*32;
        const float* src = W1 + (size_t)e*D_*H_;
        {
            int r = tid>>3, c4 = tid&7;
            float4 v = *(const float4*)(src + (size_t)(d0+r)*H_ + h0 + c4*4);
            t[r][c4*4+0]=v.x; t[r][c4*4+1]=v.y; t[r][c4*4+2]=v.z; t[r][c4*4+3]=v.w;
        }
        __syncthreads();
        __half* dst = g_w1t16 + (size_t)e*H_*D_;
#pragma unroll
        for (int q=0;q<2;q++){
            int u = tid + q*256;
            int h = u>>4, dp = u&15;
            __half2 v = __halves2half2(__float2half_rn(t[2*dp][h]), __float2half_rn(t[2*dp+1][h]));
            *(__half2*)(dst + (size_t)(h0+h)*D_ + d0 + 2*dp) = v;
        }
    } else {
        // ---- cvt_w2: [KBIG,D] -> [D,KBIG] fp16 ----
        int j = bid - GB_GATE - GB_W1;
        int bx = j & 511, by = j >> 9;
        int k0 = bx*32, d0 = by*32;
        {
            int r = tid>>3, c4 = tid&7;
            float4 v = *(const float4*)(W2 + (size_t)(k0+r)*D_ + d0 + c4*4);
            t[r][c4*4+0]=v.x; t[r][c4*4+1]=v.y; t[r][c4*4+2]=v.z; t[r][c4*4+3]=v.w;
        }
        __syncthreads();
#pragma unroll
        for (int q=0;q<2;q++){
            int u = tid + q*256;
            int d = u>>4, kp = u&15;
            __half2 v = __halves2half2(__float2half_rn(t[2*kp][d]), __float2half_rn(t[2*kp+1][d]));
            *(__half2*)(g_w2t16 + (size_t)(d0+d)*KBIG + k0 + 2*kp) = v;
        }
    }
}

// ------------------ stage loader (128 threads): 128 rows x 128B per operand, XOR swizzle ------------------
__device__ __forceinline__ void load_stage(const __half* __restrict__ A,
                                           const __half* __restrict__ B,
                                           int ldK, uint32_t sb, int k0, int tid){
#pragma unroll
    for (int i=0;i<8;i++){
        int idx = tid + i*128;
        int r = idx>>3, c = idx&7;
        uint32_t off = (uint32_t)(r*128 + ((c*16) ^ ((r&7)<<4)));
        cpa(sb + off, A + (size_t)r*ldK + k0 + c*8);
    }
#pragma unroll
    for (int i=0;i<8;i++){
        int idx = tid + i*128;
        int r = idx>>3, c = idx&7;
        uint32_t off = (uint32_t)(r*128 + ((c*16) ^ ((r&7)<<4)));
        cpa(sb + OPB + off, B + (size_t)r*ldK + k0 + c*8);
    }
}

// ------------------ fp16 HMMA GEMM (R10-proven mainloop) ------------------
// MODE 0: hs = relu(x@W1T[e]+b1)*gate  (K=D_)
// MODE 1: partial = hs@W2T over K-quarter blockIdx.z -> g_part[z] (fp16)
template<int MODE>
__global__ __launch_bounds__(128, 2)
void gemm_f16(const float* __restrict__ bias, float* __restrict__ outp){
    extern __shared__ char smem[];
    uint32_t sbase = smem_u32(smem);
    int tid = threadIdx.x;
    int lane = tid & 31, warp = tid >> 5;
    int wm = warp & 1, wn = warp >> 1;

    int n0 = blockIdx.y * BM;
    int c0 = blockIdx.x * BN;

    const __half *Ag, *Bg;
    int K, ldK;
    if (MODE == 0){
        Ag = g_x16 + (size_t)n0 * D_;
        Bg = g_w1t16 + (size_t)blockIdx.z*H_*D_ + (size_t)c0 * D_;
        K = D_; ldK = D_;
    } else {
        int kz = blockIdx.z;
        Ag = g_hs16 + (size_t)n0 * KBIG + (size_t)kz*(KBIG/KSPLIT);
        Bg = g_w2t16 + (size_t)c0 * KBIG + (size_t)kz*(KBIG/KSPLIT);
        K = KBIG/KSPLIT; ldK = KBIG;
    }
    const int NC = K / BKH;

    float acc[4][8][4];
#pragma unroll
    for (int i=0;i<4;i++)
#pragma unroll
        for (int j=0;j<8;j++)
#pragma unroll
            for (int q=0;q<4;q++) acc[i][j][q] = 0.f;

    int arow = wm*64 + (lane&15);
    uint32_t axor = (uint32_t)((arow&7)<<4);
    int brow = wn*64 + ((lane>>4)<<3) + (lane&7);
    uint32_t bxor = (uint32_t)((brow&7)<<4);
    uint32_t acol0 = (uint32_t)((lane>>4)*16);
    uint32_t bcol0 = (uint32_t)(((lane>>3)&1)*16);

    load_stage(Ag, Bg, ldK, sbase + 0*STAGE_BYTES, 0*BKH, tid);
    asm volatile("cp.async.commit_group;");
    load_stage(Ag, Bg, ldK, sbase + 1*STAGE_BYTES, 1*BKH, tid);
    asm volatile("cp.async.commit_group;");

    int sidx = 0;
    for (int kt=0; kt<NC; kt++){
        asm volatile("cp.async.wait_group 1;");
        __syncthreads();

        uint32_t st = sbase + (uint32_t)sidx*STAGE_BYTES;
        uint32_t arow0 = st + (uint32_t)(arow*128);
        uint32_t brow0 = st + (uint32_t)(OPB + brow*128);

        uint32_t af[2][4][4], bf[2][4][4];
#pragma unroll
        for (int mi=0; mi<4; mi++) ldsm4(af[0][mi], arow0 + mi*(16*128) + (acol0 ^ axor));
#pragma unroll
        for (int np=0; np<4; np++) ldsm4(bf[0][np], brow0 + np*(16*128) + (bcol0 ^ bxor));

        int snext = sidx + 2; if (snext >= NSTAGE) snext -= NSTAGE;
        if (kt+2 < NC)
            load_stage(Ag, Bg, ldK, sbase + snext*STAGE_BYTES, (kt+2)*BKH, tid);
        asm volatile("cp.async.commit_group;");

#pragma unroll
        for (int ks=0; ks<4; ks++){
            int cur = ks & 1, nxt = cur ^ 1;
            if (ks < 3){
                uint32_t ac = (uint32_t)((ks+1)*32) + acol0;
                uint32_t bc = (uint32_t)((ks+1)*32) + bcol0;
#pragma unroll
                for (int mi=0; mi<4; mi++) ldsm4(af[nxt][mi], arow0 + mi*(16*128) + (ac ^ axor));
#pragma unroll
                for (int np=0; np<4; np++) ldsm4(bf[nxt][np], brow0 + np*(16*128) + (bc ^ bxor));
            }
#pragma unroll
            for (int mi=0; mi<4; mi++)
#pragma unroll
                for (int ni=0; ni<8; ni++)
                    mma16816(acc[mi][ni], af[cur][mi], &bf[cur][ni>>1][(ni&1)*2]);
        }
        sidx = snext - 1; if (sidx < 0) sidx += NSTAGE;
    }
    asm volatile("cp.async.wait_group 0;");
    __syncthreads();

    if (MODE == 0){
        int e = blockIdx.z;
        float* bsm = (float*)smem;
        bsm[tid] = bias[(size_t)e*H_ + c0 + tid];
        __syncthreads();
#pragma unroll
        for (int mi=0; mi<4; mi++){
#pragma unroll
            for (int h=0; h<2; h++){
                int tok = n0 + wm*64 + mi*16 + (lane>>2) + h*8;
                float gt = g_gate[tok*E_ + e];
                __half* dst = g_hs16 + (size_t)tok*KBIG + (size_t)e*H_ + c0;
#pragma unroll
                for (int ni=0; ni<8; ni++){
                    int col = wn*64 + ni*8 + (lane&3)*2;
                    float v0 = fmaxf(acc[mi][ni][h*2+0] + bsm[col],   0.f) * gt;
                    float v1 = fmaxf(acc[mi][ni][h*2+1] + bsm[col+1], 0.f) * gt;
                    *(__half2*)(dst + col) = __halves2half2(__float2half_rn(v0), __float2half_rn(v1));
                }
            }
        }
    } else {
        __half* dstbase = g_part[blockIdx.z];
#pragma unroll
        for (int mi=0; mi<4; mi++){
#pragma unroll
            for (int h=0; h<2; h++){
                int tok = n0 + wm*64 + mi*16 + (lane>>2) + h*8;
                __half* dst = dstbase + (size_t)tok*D_ + c0;
#pragma unroll
                for (int ni=0; ni<8; ni++){
                    int col = wn*64 + ni*8 + (lane&3)*2;
                    *(__half2*)(dst + col) = __halves2half2(
                        __float2half_rn(acc[mi][ni][h*2+0]),
                        __float2half_rn(acc[mi][ni][h*2+1]));
                }
            }
        }
    }
}

// ------------------ reduce: out = sum_z part[z] (fp16) + sum_e gate*b2 ------------------
__global__ void reduce_kernel(const float* __restrict__ b2, float* __restrict__ outp){
    int tok = blockIdx.x;
    int c = threadIdx.x * 4;
    const float* g = g_gate + (size_t)tok*E_;
    float gt[8];
#pragma unroll
    for (int e=0;e<E_;e++) gt[e] = g[e];
    float4 r = make_float4(0.f, 0.f, 0.f, 0.f);
#pragma unroll
    for (int z=0; z<KSPLIT; z++){
        const __half2* p = (const __half2*)(g_part[z] + (size_t)tok*D_ + c);
        float2 a = __half22float2(p[0]);
        float2 b = __half22float2(p[1]);
        r.x += a.x; r.y += a.y; r.z += b.x; r.w += b.y;
    }
#pragma unroll
    for (int e=0;e<E_;e++){
        float4 bv = *(const float4*)(b2 + (size_t)e*D_ + c);
        r.x = fmaf(gt[e], bv.x, r.x);
        r.y = fmaf(gt[e], bv.y, r.y);
        r.z = fmaf(gt[e], bv.z, r.z);
        r.w = fmaf(gt[e], bv.w, r.w);
    }
    *(float4*)(outp + (size_t)tok*D_ + c) = r;
}

// ---------------------------------------------------------------------------
extern "C" void kernel_launch(void* const* d_in, const int* in_sizes, int n_in,
                              void* d_out, int out_size)
{
    const float* x  = (const float*)d_in[0];
    const float* Wg = (const float*)d_in[1];
    const float* bg = (const float*)d_in[2];
    const float* W1 = (const float*)d_in[3];
    const float* b1 = (const float*)d_in[4];
    const float* W2 = (const float*)d_in[5];
    const float* b2 = (const float*)d_in[6];
    float* out = (float*)d_out;

    cudaFuncSetAttribute(gemm_f16<0>, cudaFuncAttributeMaxDynamicSharedMemorySize, SMEM_BYTES);
    cudaFuncSetAttribute(gemm_f16<1>, cudaFuncAttributeMaxDynamicSharedMemorySize, SMEM_BYTES);

    preamble_kernel<<<GB_ALL, 256>>>(x, Wg, bg, W1, W2);

    gemm_f16<0><<<dim3(H_/BN, NTOK/BM, E_), 128, SMEM_BYTES>>>(b1, nullptr);
    gemm_f16<1><<<dim3(D_/BN, NTOK/BM, KSPLIT), 128, SMEM_BYTES>>>(nullptr, nullptr);
    reduce_kernel<<<NTOK, 256>>>(b2, out);
}

// round 17
// speedup vs baseline: 1.0398x; 1.0017x over previous
#include <cuda_runtime.h>
#include <cuda_fp16.h>
#include <stdint.h>

#define NTOK 8192
#define D_   1024
#define H_   2048
#define E_   8
#define KBIG (E_*H_)
#define KSPLIT 4

#define BM 128
#define BN 128
#define BKH 64
#define OPB (128*128)
#define STAGE_BYTES (2*OPB)
#define NSTAGE 3
#define SMEM_BYTES (NSTAGE*STAGE_BYTES)

// merged-preamble grid layout
#define GB_GATE 1024                   // 1024 blocks x 256 thr, 1 warp/token
#define GB_W1   (64*32*8)              // 16384
#define GB_W2   (512*32)               // 16384
#define GB_ALL  (GB_GATE+GB_W1+GB_W2)  // 33792

// ------------------ scratch ------------------
__device__ float g_gate[NTOK*E_];
__device__ __half g_x16[(size_t)NTOK*D_];
__device__ __half g_w1t16[(size_t)E_*H_*D_];   // [E][H][D]
__device__ __half g_w2t16[(size_t)D_*KBIG];    // [D][KBIG]
__device__ __half g_hs16[(size_t)NTOK*KBIG];   // [NTOK][KBIG]
__device__ __half g_part[KSPLIT][(size_t)NTOK*D_];   // fp16 split-K partials

// ------------------ PTX helpers ------------------
__device__ __forceinline__ uint32_t smem_u32(const void* p){
    uint32_t a;
    asm("{ .reg .u64 t; cvta.to.shared.u64 t, %1; cvt.u32.u64 %0, t; }" : "=r"(a) : "l"(p));
    return a;
}
__device__ __forceinline__ void cpa(uint32_t dst, const void* src){
    asm volatile("cp.async.cg.shared.global [%0], [%1], 16;" :: "r"(dst), "l"(src));
}
__device__ __forceinline__ void ldsm4(uint32_t* r, uint32_t addr){
    asm volatile("ldmatrix.sync.aligned.m8n8.x4.shared.b16 {%0,%1,%2,%3}, [%4];"
        : "=r"(r[0]), "=r"(r[1]), "=r"(r[2]), "=r"(r[3]) : "r"(addr));
}
__device__ __forceinline__ void mma16816(float* c, const uint32_t* a, const uint32_t* b){
    asm volatile("mma.sync.aligned.m16n8k16.row.col.f32.f16.f16.f32 "
        "{%0,%1,%2,%3}, {%4,%5,%6,%7}, {%8,%9}, {%0,%1,%2,%3};"
        : "+f"(c[0]), "+f"(c[1]), "+f"(c[2]), "+f"(c[3])
        : "r"(a[0]), "r"(a[1]), "r"(a[2]), "r"(a[3]), "r"(b[0]), "r"(b[1]));
}

// ------------------ merged preamble: gate+cvt_x | cvt_w1 | cvt_w2 ------------------
__global__ __launch_bounds__(256)
void preamble_kernel(const float* __restrict__ x,  const float* __restrict__ Wg,
                     const float* __restrict__ bg, const float* __restrict__ W1,
                     const float* __restrict__ W2){
    __shared__ float t[32][33];
    int bid = blockIdx.x;
    int tid = threadIdx.x;

    if (bid < GB_GATE){
        // ---- gate = softmax(x@Wg + bg), fused x->fp16 convert (1 warp/token) ----
        int gw = (bid*256 + tid) >> 5;
        int lane = tid & 31;
        const float* xr = x + (size_t)gw * D_;
        __half* xo = g_x16 + (size_t)gw * D_;
        float acc[E_];
#pragma unroll
        for (int e=0;e<E_;e++) acc[e]=0.f;
        for (int k=lane;k<D_;k+=32){
            float xv = xr[k];
            xo[k] = __float2half_rn(xv);
            float4 w0 = *(const float4*)(Wg + k*E_);
            float4 w1 = *(const float4*)(Wg + k*E_ + 4);
            acc[0]=fmaf(xv,w0.x,acc[0]); acc[1]=fmaf(xv,w0.y,acc[1]);
            acc[2]=fmaf(xv,w0.z,acc[2]); acc[3]=fmaf(xv,w0.w,acc[3]);
            acc[4]=fmaf(xv,w1.x,acc[4]); acc[5]=fmaf(xv,w1.y,acc[5]);
            acc[6]=fmaf(xv,w1.z,acc[6]); acc[7]=fmaf(xv,w1.w,acc[7]);
        }
#pragma unroll
        for (int e=0;e<E_;e++)
#pragma unroll
            for (int o=16;o;o>>=1) acc[e] += __shfl_xor_sync(0xFFFFFFFFu, acc[e], o);
        if (lane==0){
            float m=-1e30f;
#pragma unroll
            for (int e=0;e<E_;e++){ acc[e]+=bg[e]; m=fmaxf(m,acc[e]); }
            float s=0.f;
#pragma unroll
            for (int e=0;e<E_;e++){ acc[e]=__expf(acc[e]-m); s+=acc[e]; }
            float inv=1.f/s;
#pragma unroll
            for (int e=0;e<E_;e++) g_gate[gw*E_+e]=acc[e]*inv;
        }
    } else if (bid < GB_GATE + GB_W1){
        // ---- cvt_w1: [E,D,H] -> [E,H,D] fp16 (32x32 transpose tile) ----
        int i = bid - GB_GATE;
        int bx = i & 63, by = (i>>6) & 31, e = i >> 11;
        int h0 = bx*32, d0 = by*32;
        const float* src = W1 + (size_t)e*D_*H_;
        {
            int r = tid>>3, c4 = tid&7;
            float4 v = *(const float4*)(src + (size_t)(d0+r)*H_ + h0 + c4*4);
            t[r][c4*4+0]=v.x; t[r][c4*4+1]=v.y; t[r][c4*4+2]=v.z; t[r][c4*4+3]=v.w;
        }
        __syncthreads();
        __half* dst = g_w1t16 + (size_t)e*H_*D_;
#pragma unroll
        for (int q=0;q<2;q++){
            int u = tid + q*256;
            int h = u>>4, dp = u&15;
            __half2 v = __halves2half2(__float2half_rn(t[2*dp][h]), __float2half_rn(t[2*dp+1][h]));
            *(__half2*)(dst + (size_t)(h0+h)*D_ + d0 + 2*dp) = v;
        }
    } else {
        // ---- cvt_w2: [KBIG,D] -> [D,KBIG] fp16 ----
        int j = bid - GB_GATE - GB_W1;
        int bx = j & 511, by = j >> 9;
        int k0 = bx*32, d0 = by*32;
        {
            int r = tid>>3, c4 = tid&7;
            float4 v = *(const float4*)(W2 + (size_t)(k0+r)*D_ + d0 + c4*4);
            t[r][c4*4+0]=v.x; t[r][c4*4+1]=v.y; t[r][c4*4+2]=v.z; t[r][c4*4+3]=v.w;
        }
        __syncthreads();
#pragma unroll
        for (int q=0;q<2;q++){
            int u = tid + q*256;
            int d = u>>4, kp = u&15;
            __half2 v = __halves2half2(__float2half_rn(t[2*kp][d]), __float2half_rn(t[2*kp+1][d]));
            *(__half2*)(g_w2t16 + (size_t)(d0+d)*KBIG + k0 + 2*kp) = v;
        }
    }
}

// ------------------ stage loader (128 threads): 128 rows x 128B per operand, XOR swizzle ------------------
__device__ __forceinline__ void load_stage(const __half* __restrict__ A,
                                           const __half* __restrict__ B,
                                           int ldK, uint32_t sb, int k0, int tid){
#pragma unroll
    for (int i=0;i<8;i++){
        int idx = tid + i*128;
        int r = idx>>3, c = idx&7;
        uint32_t off = (uint32_t)(r*128 + ((c*16) ^ ((r&7)<<4)));
        cpa(sb + off, A + (size_t)r*ldK + k0 + c*8);
    }
#pragma unroll
    for (int i=0;i<8;i++){
        int idx = tid + i*128;
        int r = idx>>3, c = idx&7;
        uint32_t off = (uint32_t)(r*128 + ((c*16) ^ ((r&7)<<4)));
        cpa(sb + OPB + off, B + (size_t)r*ldK + k0 + c*8);
    }
}

// ------------------ fp16 HMMA GEMM (R10-proven mainloop) ------------------
// MODE 0: hs = relu(x@W1T[e]+b1)*gate  (K=D_)
// MODE 1: partial = hs@W2T over K-quarter blockIdx.z -> g_part[z] (fp16)
template<int MODE>
__global__ __launch_bounds__(128, 2)
void gemm_f16(const float* __restrict__ bias, float* __restrict__ outp){
    extern __shared__ char smem[];
    uint32_t sbase = smem_u32(smem);
    int tid = threadIdx.x;
    int lane = tid & 31, warp = tid >> 5;
    int wm = warp & 1, wn = warp >> 1;

    int n0 = blockIdx.y * BM;
    int c0 = blockIdx.x * BN;

    const __half *Ag, *Bg;
    int K, ldK;
    if (MODE == 0){
        Ag = g_x16 + (size_t)n0 * D_;
        Bg = g_w1t16 + (size_t)blockIdx.z*H_*D_ + (size_t)c0 * D_;
        K = D_; ldK = D_;
    } else {
        int kz = blockIdx.z;
        Ag = g_hs16 + (size_t)n0 * KBIG + (size_t)kz*(KBIG/KSPLIT);
        Bg = g_w2t16 + (size_t)c0 * KBIG + (size_t)kz*(KBIG/KSPLIT);
        K = KBIG/KSPLIT; ldK = KBIG;
    }
    const int NC = K / BKH;

    float acc[4][8][4];
#pragma unroll
    for (int i=0;i<4;i++)
#pragma unroll
        for (int j=0;j<8;j++)
#pragma unroll
            for (int q=0;q<4;q++) acc[i][j][q] = 0.f;

    int arow = wm*64 + (lane&15);
    uint32_t axor = (uint32_t)((arow&7)<<4);
    int brow = wn*64 + ((lane>>4)<<3) + (lane&7);
    uint32_t bxor = (uint32_t)((brow&7)<<4);
    uint32_t acol0 = (uint32_t)((lane>>4)*16);
    uint32_t bcol0 = (uint32_t)(((lane>>3)&1)*16);

    load_stage(Ag, Bg, ldK, sbase + 0*STAGE_BYTES, 0*BKH, tid);
    asm volatile("cp.async.commit_group;");
    load_stage(Ag, Bg, ldK, sbase + 1*STAGE_BYTES, 1*BKH, tid);
    asm volatile("cp.async.commit_group;");

    int sidx = 0;
    for (int kt=0; kt<NC; kt++){
        asm volatile("cp.async.wait_group 1;");
        __syncthreads();

        uint32_t st = sbase + (uint32_t)sidx*STAGE_BYTES;
        uint32_t arow0 = st + (uint32_t)(arow*128);
        uint32_t brow0 = st + (uint32_t)(OPB + brow*128);

        uint32_t af[2][4][4], bf[2][4][4];
#pragma unroll
        for (int mi=0; mi<4; mi++) ldsm4(af[0][mi], arow0 + mi*(16*128) + (acol0 ^ axor));
#pragma unroll
        for (int np=0; np<4; np++) ldsm4(bf[0][np], brow0 + np*(16*128) + (bcol0 ^ bxor));

        int snext = sidx + 2; if (snext >= NSTAGE) snext -= NSTAGE;
        if (kt+2 < NC)
            load_stage(Ag, Bg, ldK, sbase + snext*STAGE_BYTES, (kt+2)*BKH, tid);
        asm volatile("cp.async.commit_group;");

#pragma unroll
        for (int ks=0; ks<4; ks++){
            int cur = ks & 1, nxt = cur ^ 1;
            if (ks < 3){
                uint32_t ac = (uint32_t)((ks+1)*32) + acol0;
                uint32_t bc = (uint32_t)((ks+1)*32) + bcol0;
#pragma unroll
                for (int mi=0; mi<4; mi++) ldsm4(af[nxt][mi], arow0 + mi*(16*128) + (ac ^ axor));
#pragma unroll
                for (int np=0; np<4; np++) ldsm4(bf[nxt][np], brow0 + np*(16*128) + (bc ^ bxor));
            }
#pragma unroll
            for (int mi=0; mi<4; mi++)
#pragma unroll
                for (int ni=0; ni<8; ni++)
                    mma16816(acc[mi][ni], af[cur][mi], &bf[cur][ni>>1][(ni&1)*2]);
        }
        sidx = snext - 1; if (sidx < 0) sidx += NSTAGE;
    }
    asm volatile("cp.async.wait_group 0;");
    __syncthreads();

    if (MODE == 0){
        int e = blockIdx.z;
        float* bsm = (float*)smem;
        bsm[tid] = bias[(size_t)e*H_ + c0 + tid];
        __syncthreads();
#pragma unroll
        for (int mi=0; mi<4; mi++){
#pragma unroll
            for (int h=0; h<2; h++){
                int tok = n0 + wm*64 + mi*16 + (lane>>2) + h*8;
                float gt = g_gate[tok*E_ + e];
                __half* dst = g_hs16 + (size_t)tok*KBIG + (size_t)e*H_ + c0;
#pragma unroll
                for (int ni=0; ni<8; ni++){
                    int col = wn*64 + ni*8 + (lane&3)*2;
                    float v0 = fmaxf(acc[mi][ni][h*2+0] + bsm[col],   0.f) * gt;
                    float v1 = fmaxf(acc[mi][ni][h*2+1] + bsm[col+1], 0.f) * gt;
                    *(__half2*)(dst + col) = __halves2half2(__float2half_rn(v0), __float2half_rn(v1));
                }
            }
        }
    } else {
        __half* dstbase = g_part[blockIdx.z];
#pragma unroll
        for (int mi=0; mi<4; mi++){
#pragma unroll
            for (int h=0; h<2; h++){
                int tok = n0 + wm*64 + mi*16 + (lane>>2) + h*8;
                __half* dst = dstbase + (size_t)tok*D_ + c0;
#pragma unroll
                for (int ni=0; ni<8; ni++){
                    int col = wn*64 + ni*8 + (lane&3)*2;
                    *(__half2*)(dst + col) = __halves2half2(
                        __float2half_rn(acc[mi][ni][h*2+0]),
                        __float2half_rn(acc[mi][ni][h*2+1]));
                }
            }
        }
    }
}

// ------------------ reduce: out = sum_z part[z] (fp16) + sum_e gate*b2 ------------------
__global__ void reduce_kernel(const float* __restrict__ b2, float* __restrict__ outp){
    int tok = blockIdx.x;
    int c = threadIdx.x * 4;
    const float* g = g_gate + (size_t)tok*E_;
    float gt[8];
#pragma unroll
    for (int e=0;e<E_;e++) gt[e] = g[e];
    float4 r = make_float4(0.f, 0.f, 0.f, 0.f);
#pragma unroll
    for (int z=0; z<KSPLIT; z++){
        const __half2* p = (const __half2*)(g_part[z] + (size_t)tok*D_ + c);
        float2 a = __half22float2(p[0]);
        float2 b = __half22float2(p[1]);
        r.x += a.x; r.y += a.y; r.z += b.x; r.w += b.y;
    }
#pragma unroll
    for (int e=0;e<E_;e++){
        float4 bv = *(const float4*)(b2 + (size_t)e*D_ + c);
        r.x = fmaf(gt[e], bv.x, r.x);
        r.y = fmaf(gt[e], bv.y, r.y);
        r.z = fmaf(gt[e], bv.z, r.z);
        r.w = fmaf(gt[e], bv.w, r.w);
    }
    *(float4*)(outp + (size_t)tok*D_ + c) = r;
}

// ---------------------------------------------------------------------------
extern "C" void kernel_launch(void* const* d_in, const int* in_sizes, int n_in,
                              void* d_out, int out_size)
{
    const float* x  = (const float*)d_in[0];
    const float* Wg = (const float*)d_in[1];
    const float* bg = (const float*)d_in[2];
    const float* W1 = (const float*)d_in[3];
    const float* b1 = (const float*)d_in[4];
    const float* W2 = (const float*)d_in[5];
    const float* b2 = (const float*)d_in[6];
    float* out = (float*)d_out;

    cudaFuncSetAttribute(gemm_f16<0>, cudaFuncAttributeMaxDynamicSharedMemorySize, SMEM_BYTES);
    cudaFuncSetAttribute(gemm_f16<1>, cudaFuncAttributeMaxDynamicSharedMemorySize, SMEM_BYTES);

    preamble_kernel<<<GB_ALL, 256>>>(x, Wg, bg, W1, W2);

    gemm_f16<0><<<dim3(H_/BN, NTOK/BM, E_), 128, SMEM_BYTES>>>(b1, nullptr);
    gemm_f16<1><<<dim3(D_/BN, NTOK/BM, KSPLIT), 128, SMEM_BYTES>>>(nullptr, nullptr);
    reduce_kernel<<<NTOK, 256>>>(b2, out);
}